// round 1
// baseline (speedup 1.0000x reference)
#include <cuda_runtime.h>
#include <math.h>

#define NT 1024
#define CD 768
#define NH 16
#define DH 48
#define HD 1536
#define CPD 128

// ---------------- scratch (device globals; no allocations allowed) ----------
__device__ __align__(16) float g_lna[NT*CD];
__device__ __align__(16) float g_sn1[NT*CD];
__device__ __align__(16) float g_sn2[NT*CD];
__device__ __align__(16) float g_tg[NT*CD];
__device__ __align__(16) float g_tk[NT*CD];
__device__ __align__(16) float g_an[NT*CD];
__device__ __align__(16) float g_q[NT*CD];
__device__ __align__(16) float g_k[NT*CD];
__device__ __align__(16) float g_v[NT*CD];
__device__ __align__(16) float g_gate[NT*CD];
__device__ __align__(16) float g_o[NT*CD];
__device__ __align__(16) float g_attout[NT*CD];
__device__ __align__(16) float g_bout[NT*CD];
__device__ __align__(16) float g_h1[NT*HD];
__device__ __align__(16) float g_h2[NT*HD];
__device__ __align__(16) float g_t3[NT*CD];
__device__ __align__(16) float g_ts[NT*CD];
__device__ __align__(16) float g_wgp[CPD*NH];
__device__ __align__(16) float g_cc[2*NH];
__device__ __align__(16) float g_bias[(size_t)NH*NT*NT];   // 64 MB [h][q][k]

__device__ __forceinline__ float sigm(float x) { return 1.f/(1.f+__expf(-x)); }

// ---------------- LayerNorm of a and s; sn1 = LN(s)*sg1, sn2 = LN(s)*sg2 ----
__global__ void ln_kernel(const float* __restrict__ a, const float* __restrict__ s,
                          const float* __restrict__ sg1, const float* __restrict__ sg2)
{
    int r = blockIdx.x, t = threadIdx.x;
    const float* ar = a + (size_t)r*CD;
    const float* sr = s + (size_t)r*CD;
    float va[3], vs[3];
    float s0=0.f,s1=0.f,s2=0.f,s3=0.f;
#pragma unroll
    for (int i=0;i<3;i++){
        va[i]=ar[t+256*i]; vs[i]=sr[t+256*i];
        s0+=va[i]; s1+=va[i]*va[i]; s2+=vs[i]; s3+=vs[i]*vs[i];
    }
    __shared__ float red[4][8];
    int lane=t&31, w=t>>5;
#pragma unroll
    for (int o=16;o;o>>=1){
        s0+=__shfl_xor_sync(0xffffffffu,s0,o);
        s1+=__shfl_xor_sync(0xffffffffu,s1,o);
        s2+=__shfl_xor_sync(0xffffffffu,s2,o);
        s3+=__shfl_xor_sync(0xffffffffu,s3,o);
    }
    if (lane==0){ red[0][w]=s0; red[1][w]=s1; red[2][w]=s2; red[3][w]=s3; }
    __syncthreads();
    float S0=0.f,S1=0.f,S2=0.f,S3=0.f;
#pragma unroll
    for (int i=0;i<8;i++){ S0+=red[0][i]; S1+=red[1][i]; S2+=red[2][i]; S3+=red[3][i]; }
    float mua=S0*(1.f/768.f), rsa=rsqrtf(S1*(1.f/768.f)-mua*mua+1e-5f);
    float mus=S2*(1.f/768.f), rss=rsqrtf(S3*(1.f/768.f)-mus*mus+1e-5f);
#pragma unroll
    for (int i=0;i<3;i++){
        int c=t+256*i; size_t idx=(size_t)r*CD+c;
        g_lna[idx]=(va[i]-mua)*rsa;
        float sv=(vs[i]-mus)*rss;
        g_sn1[idx]=sv*sg1[c];
        g_sn2[idx]=sv*sg2[c];
    }
}

// ---------------- generic SGEMM: C[M,N] = A[M,K] @ B[K,N] (+bias[N]) --------
// 64x64 tile, BK=16, 256 threads, 4x4 per thread. All dims divisible.
__global__ void __launch_bounds__(256) sgemm_kernel(
    const float* __restrict__ A, const float* __restrict__ B,
    const float* __restrict__ biasv, float* __restrict__ Cmat,
    int M, int Nn, int K)
{
    __shared__ __align__(16) float As[16][64];
    __shared__ __align__(16) float Bs[16][64];
    int tid = threadIdx.x;
    int tx = tid & 15, ty = tid >> 4;
    int row0 = blockIdx.y << 6, col0 = blockIdx.x << 6;
    int ar = tid >> 2, ac = (tid & 3) << 2;
    const float* Ag = A + (size_t)(row0 + ar)*K + ac;
    const float* Bg = B + (size_t)(tid >> 4)*Nn + col0 + ((tid & 15) << 2);
    float acc[4][4] = {};
    for (int k0 = 0; k0 < K; k0 += 16) {
        float4 av = *(const float4*)(Ag + k0);
        float4 bv = *(const float4*)(Bg + (size_t)k0*Nn);
        __syncthreads();
        As[ac+0][ar]=av.x; As[ac+1][ar]=av.y; As[ac+2][ar]=av.z; As[ac+3][ar]=av.w;
        *(float4*)&Bs[tid>>4][(tid&15)<<2] = bv;
        __syncthreads();
#pragma unroll
        for (int kk = 0; kk < 16; kk++) {
            float4 a4 = *(const float4*)&As[kk][ty<<2];
            float4 b4 = *(const float4*)&Bs[kk][tx<<2];
            acc[0][0]+=a4.x*b4.x; acc[0][1]+=a4.x*b4.y; acc[0][2]+=a4.x*b4.z; acc[0][3]+=a4.x*b4.w;
            acc[1][0]+=a4.y*b4.x; acc[1][1]+=a4.y*b4.y; acc[1][2]+=a4.y*b4.z; acc[1][3]+=a4.y*b4.w;
            acc[2][0]+=a4.z*b4.x; acc[2][1]+=a4.z*b4.y; acc[2][2]+=a4.z*b4.z; acc[2][3]+=a4.z*b4.w;
            acc[3][0]+=a4.w*b4.x; acc[3][1]+=a4.w*b4.y; acc[3][2]+=a4.w*b4.z; acc[3][3]+=a4.w*b4.w;
        }
    }
    int cbase = col0 + (tx<<2);
    float4 bb = make_float4(0.f,0.f,0.f,0.f);
    if (biasv) bb = *(const float4*)(biasv + cbase);
#pragma unroll
    for (int i=0;i<4;i++){
        int r = row0 + (ty<<2) + i;
        float4 vout;
        vout.x = acc[i][0]+bb.x; vout.y = acc[i][1]+bb.y;
        vout.z = acc[i][2]+bb.z; vout.w = acc[i][3]+bb.w;
        *(float4*)(Cmat + (size_t)r*Nn + cbase) = vout;
    }
}

// ---------------- adaLN combine: out = sigmoid(tg+bg)*lna + tk --------------
__global__ void adaln_combine_kernel(const float* __restrict__ tg,
                                     const float* __restrict__ bgv,
                                     const float* __restrict__ tk,
                                     float* __restrict__ outp)
{
    int i = blockIdx.x*256 + threadIdx.x;
    int c = i % CD;
    outp[i] = sigm(tg[i]+bgv[c])*g_lna[i] + tk[i];
}

// ---------------- pair-bias precompute: wgp = gp*wp; c1,c2 ------------------
__global__ void pair_prep_kernel(const float* __restrict__ gp,
                                 const float* __restrict__ bp,
                                 const float* __restrict__ wp)
{
    int j = threadIdx.x;  // 128
    for (int h=0; h<NH; h++) g_wgp[j*NH+h] = gp[j]*wp[j*NH+h];
    __syncthreads();
    if (j < NH) {
        float c1=0.f, c2=0.f;
        for (int jj=0; jj<CPD; jj++){ c1 += bp[jj]*wp[jj*NH+j]; c2 += g_wgp[jj*NH+j]; }
        g_cc[j]=c1; g_cc[NH+j]=c2;
    }
}

// ---------------- pair bias: bias[h,q,k] = LN(pair)@wp + beta ---------------
// one warp per pair; z[h] = rs*dot(x,wgp[:,h]) - mu*rs*c2[h] + c1[h]
__global__ void __launch_bounds__(256) pair_bias_kernel(
    const float* __restrict__ pair, const float* __restrict__ beta)
{
    __shared__ float wgp_s[CPD][NH+1];
    __shared__ float cs[2*NH];
    __shared__ float zs[8][NH];
    int t = threadIdx.x;
    for (int idx=t; idx<CPD*NH; idx+=256){ int j=idx>>4, h=idx&15; wgp_s[j][h]=g_wgp[idx]; }
    if (t < 2*NH) cs[t]=g_cc[t];
    __syncthreads();
    int w = t>>5, lane = t&31;
    int pq = blockIdx.y, pk = (blockIdx.x<<3) + w;
    const float4 x = *(const float4*)(pair + (((size_t)pq<<10)+pk)*CPD + (lane<<2));
    float sm = x.x+x.y+x.z+x.w;
    float sq = x.x*x.x + x.y*x.y + x.z*x.z + x.w*x.w;
#pragma unroll
    for (int o=16;o;o>>=1){
        sm += __shfl_xor_sync(0xffffffffu, sm, o);
        sq += __shfl_xor_sync(0xffffffffu, sq, o);
    }
    float mu = sm*(1.f/128.f);
    float rs = rsqrtf(sq*(1.f/128.f) - mu*mu + 1e-5f);
    float acc[NH];
    int j0 = lane<<2;
#pragma unroll
    for (int h=0; h<NH; h++)
        acc[h] = x.x*wgp_s[j0][h] + x.y*wgp_s[j0+1][h] + x.z*wgp_s[j0+2][h] + x.w*wgp_s[j0+3][h];
#pragma unroll
    for (int o=16;o;o>>=1){
#pragma unroll
        for (int h=0; h<NH; h++) acc[h] += __shfl_xor_sync(0xffffffffu, acc[h], o);
    }
    if (lane < NH) zs[w][lane] = rs*acc[lane] - mu*rs*cs[NH+lane] + cs[lane];
    __syncthreads();
    if (t < 128) {
        int h = t>>3, kk = t&7;
        int pkk = (blockIdx.x<<3) + kk;
        g_bias[((size_t)h<<20) + ((size_t)pq<<10) + pkk] = zs[kk][h] + beta[((size_t)pq<<10)+pkk];
    }
}

// ---------------- flash attention: o[q, h*48+d] -----------------------------
// 128 threads: 64 q-rows x 2 k-halves (split-K, merged via smem).
__global__ void __launch_bounds__(128) attn_kernel(
    const float* __restrict__ q, const float* __restrict__ k,
    const float* __restrict__ v)
{
    __shared__ __align__(16) float pool[6144];   // K [2][32][48] @0, V @3072
    __shared__ float Ms[64], Ls[64];
    int t = threadIdx.x;
    int half = t>>6, ql = t&63;
    int h = blockIdx.y;
    int qr = (blockIdx.x<<6) + ql;
    float qv[48];
#pragma unroll
    for (int d=0; d<48; d++) qv[d] = q[(size_t)qr*CD + h*48 + d]*0.14433756729740643f;
    float m = -1e30f, l = 0.f, acc[48];
#pragma unroll
    for (int d=0; d<48; d++) acc[d]=0.f;
    int kb = half<<9;
    const float* brow = g_bias + ((size_t)h<<20) + ((size_t)qr<<10) + kb;
    for (int kt=0; kt<512; kt+=32) {
        __syncthreads();
#pragma unroll
        for (int it=0; it<6; it++) {
            int i4 = t + (it<<7);            // 0..767 float4 slots
            int d4 = i4 % 12;
            int rem = i4 / 12;
            int j = rem & 31, hh = rem >> 5;
            int krow = (hh<<9) + kt + j;
            ((float4*)pool)[i4]      = *(const float4*)(k + (size_t)krow*CD + h*48 + (d4<<2));
            ((float4*)pool)[768+i4]  = *(const float4*)(v + (size_t)krow*CD + h*48 + (d4<<2));
        }
        __syncthreads();
        float bb[32];
#pragma unroll
        for (int i=0;i<8;i++){
            float4 b4 = *(const float4*)(brow + kt + (i<<2));
            bb[i*4]=b4.x; bb[i*4+1]=b4.y; bb[i*4+2]=b4.z; bb[i*4+3]=b4.w;
        }
        const float* Kt = pool + half*1536;
        const float* Vt = pool + 3072 + half*1536;
        for (int j=0; j<32; j++) {
            const float4* kr4 = (const float4*)(Kt + j*48);
            float sd = 0.f;
#pragma unroll
            for (int d4=0; d4<12; d4++){
                float4 kk4 = kr4[d4];
                sd += qv[d4*4]*kk4.x + qv[d4*4+1]*kk4.y + qv[d4*4+2]*kk4.z + qv[d4*4+3]*kk4.w;
            }
            float sc = sd + bb[j];
            if (sc > m) {
                float corr = __expf(m - sc);
                l *= corr;
#pragma unroll
                for (int d=0; d<48; d++) acc[d] *= corr;
                m = sc;
            }
            float p = __expf(sc - m);
            l += p;
            const float4* vr4 = (const float4*)(Vt + j*48);
#pragma unroll
            for (int d4=0; d4<12; d4++){
                float4 vv4 = vr4[d4];
                acc[d4*4]   += p*vv4.x; acc[d4*4+1] += p*vv4.y;
                acc[d4*4+2] += p*vv4.z; acc[d4*4+3] += p*vv4.w;
            }
        }
    }
    __syncthreads();
    if (half == 1) {
        Ms[ql]=m; Ls[ql]=l;
#pragma unroll
        for (int d=0; d<48; d++) pool[ql*48+d]=acc[d];
    }
    __syncthreads();
    if (half == 0) {
        float m2=Ms[ql], l2=Ls[ql];
        float mn=fmaxf(m,m2);
        float c1=__expf(m-mn), c2=__expf(m2-mn);
        float inv=1.f/(l*c1 + l2*c2);
#pragma unroll
        for (int d=0; d<48; d++)
            g_o[(size_t)qr*CD + h*48 + d] = (acc[d]*c1 + pool[ql*48+d]*c2)*inv;
    }
}

// ---------------- small elementwise kernels ---------------------------------
__global__ void gate_mul_kernel() {
    int i = blockIdx.x*256 + threadIdx.x;
    g_o[i] *= sigm(g_gate[i]);
}
__global__ void bout_kernel(const float* __restrict__ bso) {
    int i = blockIdx.x*256 + threadIdx.x;
    int c = i % CD;
    g_bout[i] = sigm(g_ts[i]+bso[c])*g_attout[i];
}
__global__ void swiglu_kernel() {
    int i = blockIdx.x*256 + threadIdx.x;   // < NT*HD
    float x = g_h1[i];
    g_h1[i] = x*sigm(x)*g_h2[i];
}
__global__ void final_kernel(const float* __restrict__ bs2, float* __restrict__ outp) {
    int i = blockIdx.x*256 + threadIdx.x;
    int c = i % CD;
    outp[i] = g_bout[i] + sigm(g_ts[i]+bs2[c])*g_t3[i];
}

// ---------------- launch ----------------------------------------------------
extern "C" void kernel_launch(void* const* d_in, const int* in_sizes, int n_in,
                              void* d_out, int out_size)
{
    (void)in_sizes; (void)n_in; (void)out_size;
    const float* a     = (const float*)d_in[0];
    const float* s     = (const float*)d_in[1];
    const float* pair  = (const float*)d_in[2];
    const float* beta  = (const float*)d_in[3];
    const float* sg1   = (const float*)d_in[4];
    const float* wg1   = (const float*)d_in[5];
    const float* bg1   = (const float*)d_in[6];
    const float* wsk1  = (const float*)d_in[7];
    const float* wq    = (const float*)d_in[8];
    const float* bq    = (const float*)d_in[9];
    const float* wk    = (const float*)d_in[10];
    const float* wv    = (const float*)d_in[11];
    const float* gp    = (const float*)d_in[12];
    const float* bp    = (const float*)d_in[13];
    const float* wp    = (const float*)d_in[14];
    const float* wgate = (const float*)d_in[15];
    const float* wo    = (const float*)d_in[16];
    const float* wso   = (const float*)d_in[17];
    const float* bso   = (const float*)d_in[18];
    const float* sg2   = (const float*)d_in[19];
    const float* wg2   = (const float*)d_in[20];
    const float* bg2   = (const float*)d_in[21];
    const float* wsk2  = (const float*)d_in[22];
    const float* w1    = (const float*)d_in[23];
    const float* w2    = (const float*)d_in[24];
    const float* w3    = (const float*)d_in[25];
    const float* ws2   = (const float*)d_in[26];
    const float* bs2   = (const float*)d_in[27];

    float *p_sn1,*p_sn2,*p_tg,*p_tk,*p_an,*p_q,*p_k,*p_v,*p_gate,*p_o,*p_attout,*p_ts,*p_h1,*p_h2,*p_t3;
    cudaGetSymbolAddress((void**)&p_sn1,   g_sn1);
    cudaGetSymbolAddress((void**)&p_sn2,   g_sn2);
    cudaGetSymbolAddress((void**)&p_tg,    g_tg);
    cudaGetSymbolAddress((void**)&p_tk,    g_tk);
    cudaGetSymbolAddress((void**)&p_an,    g_an);
    cudaGetSymbolAddress((void**)&p_q,     g_q);
    cudaGetSymbolAddress((void**)&p_k,     g_k);
    cudaGetSymbolAddress((void**)&p_v,     g_v);
    cudaGetSymbolAddress((void**)&p_gate,  g_gate);
    cudaGetSymbolAddress((void**)&p_o,     g_o);
    cudaGetSymbolAddress((void**)&p_attout,g_attout);
    cudaGetSymbolAddress((void**)&p_ts,    g_ts);
    cudaGetSymbolAddress((void**)&p_h1,    g_h1);
    cudaGetSymbolAddress((void**)&p_h2,    g_h2);
    cudaGetSymbolAddress((void**)&p_t3,    g_t3);

    dim3 g768(12, 16), gHID(24, 16);

    ln_kernel<<<NT, 256>>>(a, s, sg1, sg2);
    pair_prep_kernel<<<1, 128>>>(gp, bp, wp);

    // ---- AttentionPairBias ----
    sgemm_kernel<<<g768, 256>>>(p_sn1, wg1, nullptr, p_tg, NT, CD, CD);
    sgemm_kernel<<<g768, 256>>>(p_sn1, wsk1, nullptr, p_tk, NT, CD, CD);
    adaln_combine_kernel<<<NT*CD/256, 256>>>(p_tg, bg1, p_tk, p_an);
    sgemm_kernel<<<g768, 256>>>(p_an, wq, bq, p_q, NT, CD, CD);
    sgemm_kernel<<<g768, 256>>>(p_an, wk, nullptr, p_k, NT, CD, CD);
    sgemm_kernel<<<g768, 256>>>(p_an, wv, nullptr, p_v, NT, CD, CD);
    sgemm_kernel<<<g768, 256>>>(p_an, wgate, nullptr, p_gate, NT, CD, CD);
    pair_bias_kernel<<<dim3(128, 1024), 256>>>(pair, beta);
    attn_kernel<<<dim3(16, 16), 128>>>(p_q, p_k, p_v);
    gate_mul_kernel<<<NT*CD/256, 256>>>();
    sgemm_kernel<<<g768, 256>>>(p_o, wo, nullptr, p_attout, NT, CD, CD);
    sgemm_kernel<<<g768, 256>>>(s, wso, nullptr, p_ts, NT, CD, CD);
    bout_kernel<<<NT*CD/256, 256>>>(bso);

    // ---- ConditionedTransitionBlock ----
    sgemm_kernel<<<g768, 256>>>(p_sn2, wg2, nullptr, p_tg, NT, CD, CD);
    sgemm_kernel<<<g768, 256>>>(p_sn2, wsk2, nullptr, p_tk, NT, CD, CD);
    adaln_combine_kernel<<<NT*CD/256, 256>>>(p_tg, bg2, p_tk, p_an);
    sgemm_kernel<<<gHID, 256>>>(p_an, w1, nullptr, p_h1, NT, HD, CD);
    sgemm_kernel<<<gHID, 256>>>(p_an, w2, nullptr, p_h2, NT, HD, CD);
    swiglu_kernel<<<NT*HD/256, 256>>>();
    sgemm_kernel<<<g768, 256>>>(p_h1, w3, nullptr, p_t3, NT, CD, HD);
    sgemm_kernel<<<g768, 256>>>(s, ws2, nullptr, p_ts, NT, CD, CD);
    final_kernel<<<NT*CD/256, 256>>>(bs2, (float*)d_out);
}